// round 2
// baseline (speedup 1.0000x reference)
#include <cuda_runtime.h>
#include <math.h>

#define Bc    32
#define Sc    512
#define Hc    768
#define Wc    128
#define Gc    4
#define NHc   4
#define HDc   192
#define FFc   2048
#define NLc   2
#define NLABc 6
#define LW    129
#define MROWS (Bc*LW)     /* 4128 */
#define H3    (3*Hc)      /* 2304 */

// ---------------- scratch (device globals; no allocation allowed) ----------
__device__ float g_x  [MROWS*Hc];
__device__ float g_qkv[MROWS*H3];
__device__ float g_ctx[MROWS*Hc];
__device__ float g_y  [MROWS*Hc];
__device__ float g_ffh[MROWS*FFc];
__device__ float g_wvalid[Bc*Wc];
__device__ int   g_mtype;   // 0=f32, 1=u8, 2=i32
__device__ int   g_vtype;

// ---------------- dtype detection for bool inputs --------------------------
// group_token_mask: mask[...,0] is always 1 (glen>=1). word_valid: first 64
// words of each batch are 1 (nwords >= W/2). So:
//   float32 buffer -> word 0x3f800000 appears
//   uint8 buffer   -> some 4-byte word has value >1 (packed 0x01 bytes)
//   int32 buffer   -> all words in {0,1}
__global__ void detect_kernel(const unsigned int* __restrict__ gm,
                              const unsigned int* __restrict__ wv) {
    __shared__ int fm, bm_, fv, bv;
    int tid = threadIdx.x;
    if (tid == 0) { fm = 0; bm_ = 0; fv = 0; bv = 0; }
    __syncthreads();
    // safe read lengths: gmask has >=16384 bytes, word_valid >=4096 bytes
    for (int i = tid; i < 4096; i += 256) {
        unsigned v = gm[i];
        if (v == 0x3f800000u) atomicOr(&fm, 1);
        else if (v > 1u)      atomicOr(&bm_, 1);
    }
    for (int i = tid; i < 1024; i += 256) {
        unsigned v = wv[i];
        if (v == 0x3f800000u) atomicOr(&fv, 1);
        else if (v > 1u)      atomicOr(&bv, 1);
    }
    __syncthreads();
    if (tid == 0) {
        g_mtype = fm ? 0 : (bm_ ? 1 : 2);
        g_vtype = fv ? 0 : (bv ? 1 : 2);
    }
}

__device__ __forceinline__ float read_flag(const void* p, int t, int i) {
    if (t == 0) return ((const float*)p)[i];
    if (t == 1) return (float)((const unsigned char*)p)[i];
    return (float)((const int*)p)[i];
}

// ---------------- build x = [cls ; word embeddings], wvalid -----------------
__global__ void build_kernel(const float* __restrict__ hidden,
                             const int*   __restrict__ widx,
                             const void*  __restrict__ gmask,
                             const void*  __restrict__ wvin,
                             float* __restrict__ x,
                             float* __restrict__ wvalid) {
    int qi  = blockIdx.x;   // 0..128
    int b   = blockIdx.y;
    int tid = threadIdx.x;  // 256
    float* xr = x + ((size_t)(b*LW) + qi) * Hc;
    if (qi == 0) {
        const float* hr = hidden + (size_t)b * Sc * Hc;
        xr[tid] = hr[tid]; xr[tid+256] = hr[tid+256]; xr[tid+512] = hr[tid+512];
        return;
    }
    int w = qi - 1;
    int mt = g_mtype, vt = g_vtype;
    int base = (b*Wc + w) * Gc;
    float mk0 = read_flag(gmask, mt, base+0);
    float mk1 = read_flag(gmask, mt, base+1);
    float mk2 = read_flag(gmask, mt, base+2);
    float mk3 = read_flag(gmask, mt, base+3);
    float cnt = mk0 + mk1 + mk2 + mk3;
    float valid = read_flag(wvin, vt, b*Wc + w);
    if (tid == 0) wvalid[b*Wc + w] = valid;
    float invc = valid / fmaxf(cnt, 1.f);
    const float* hb = hidden + (size_t)b * Sc * Hc;
    const float* r0 = hb + (size_t)widx[base+0] * Hc;
    const float* r1 = hb + (size_t)widx[base+1] * Hc;
    const float* r2 = hb + (size_t)widx[base+2] * Hc;
    const float* r3 = hb + (size_t)widx[base+3] * Hc;
    for (int d = tid; d < Hc; d += 256) {
        float acc = mk0*r0[d] + mk1*r1[d] + mk2*r2[d] + mk3*r3[d];
        xr[d] = acc * invc;
    }
}

// ---------------- tiled SGEMM: C[M,N] = A[M,K] @ W[N,K]^T + bias (+res/relu)
// EPI: 0 = bias, 1 = bias+relu, 2 = bias+residual
template<int EPI>
__global__ void sgemm_kernel(const float* __restrict__ A,
                             const float* __restrict__ Wt,
                             const float* __restrict__ bias,
                             const float* __restrict__ res,
                             float* __restrict__ C,
                             int M_, int N_, int K_) {
    __shared__ float As[8][128];
    __shared__ float Bs[8][128];
    const int tid = threadIdx.x;     // 256
    const int bm = blockIdx.y * 128;
    const int bn = blockIdx.x * 128;
    const int ty = tid >> 4;         // 0..15
    const int tx = tid & 15;         // 0..15
    const int lrow = tid >> 1;       // 0..127
    const int lcol = (tid & 1) << 2; // 0 or 4

    const bool arow_ok = (bm + lrow) < M_;
    const float* Ap = A  + (size_t)(bm + lrow) * K_ + lcol;
    const float* Bp = Wt + (size_t)(bn + lrow) * K_ + lcol;

    float4 apre = arow_ok ? *(const float4*)Ap : make_float4(0.f,0.f,0.f,0.f);
    float4 bpre = *(const float4*)Bp;

    float acc[8][8];
    #pragma unroll
    for (int i = 0; i < 8; i++)
        #pragma unroll
        for (int j = 0; j < 8; j++) acc[i][j] = 0.f;

    const int ktiles = K_ >> 3;
    for (int kt = 0; kt < ktiles; kt++) {
        As[lcol+0][lrow]=apre.x; As[lcol+1][lrow]=apre.y;
        As[lcol+2][lrow]=apre.z; As[lcol+3][lrow]=apre.w;
        Bs[lcol+0][lrow]=bpre.x; Bs[lcol+1][lrow]=bpre.y;
        Bs[lcol+2][lrow]=bpre.z; Bs[lcol+3][lrow]=bpre.w;
        __syncthreads();
        if (kt + 1 < ktiles) {
            const float* An = Ap + (kt+1)*8;
            apre = arow_ok ? *(const float4*)An : make_float4(0.f,0.f,0.f,0.f);
            bpre = *(const float4*)(Bp + (kt+1)*8);
        }
        #pragma unroll
        for (int k = 0; k < 8; k++) {
            float4 a0 = *(const float4*)&As[k][ty<<2];
            float4 a1 = *(const float4*)&As[k][64+(ty<<2)];
            float4 b0 = *(const float4*)&Bs[k][tx<<2];
            float4 b1 = *(const float4*)&Bs[k][64+(tx<<2)];
            float ar[8] = {a0.x,a0.y,a0.z,a0.w,a1.x,a1.y,a1.z,a1.w};
            float br[8] = {b0.x,b0.y,b0.z,b0.w,b1.x,b1.y,b1.z,b1.w};
            #pragma unroll
            for (int i = 0; i < 8; i++)
                #pragma unroll
                for (int j = 0; j < 8; j++)
                    acc[i][j] = fmaf(ar[i], br[j], acc[i][j]);
        }
        __syncthreads();
    }

    #pragma unroll
    for (int ih = 0; ih < 2; ih++) {
        #pragma unroll
        for (int r = 0; r < 4; r++) {
            int m = bm + ih*64 + (ty<<2) + r;
            if (m >= M_) continue;
            #pragma unroll
            for (int jh = 0; jh < 2; jh++) {
                int n = bn + jh*64 + (tx<<2);
                float4 v;
                v.x = acc[ih*4+r][jh*4+0];
                v.y = acc[ih*4+r][jh*4+1];
                v.z = acc[ih*4+r][jh*4+2];
                v.w = acc[ih*4+r][jh*4+3];
                float4 bi = *(const float4*)&bias[n];
                v.x += bi.x; v.y += bi.y; v.z += bi.z; v.w += bi.w;
                if (EPI == 2) {
                    float4 rr = *(const float4*)&res[(size_t)m*N_ + n];
                    v.x += rr.x; v.y += rr.y; v.z += rr.z; v.w += rr.w;
                }
                if (EPI == 1) {
                    v.x = fmaxf(v.x, 0.f); v.y = fmaxf(v.y, 0.f);
                    v.z = fmaxf(v.z, 0.f); v.w = fmaxf(v.w, 0.f);
                }
                *(float4*)&C[(size_t)m*N_ + n] = v;
            }
        }
    }
}

// ---------------- attention: one block per (b, h, q) ------------------------
__global__ void attn_kernel(const float* __restrict__ qkv,
                            const float* __restrict__ wvalid,
                            float* __restrict__ ctx) {
    int qi  = blockIdx.x;   // 0..128
    int h   = blockIdx.y;   // 0..3
    int b   = blockIdx.z;   // 0..31
    int tid = threadIdx.x;  // 128
    __shared__ float sq[HDc];
    __shared__ float sc[LW];
    __shared__ float red[128];

    const float* qrow = qkv + (size_t)(b*LW + qi) * H3 + h*HDc;
    for (int d = tid; d < HDc; d += 128) sq[d] = qrow[d];
    __syncthreads();

    const float scale = rsqrtf((float)HDc);
    for (int kk = tid; kk < LW; kk += 128) {
        bool valid = (kk == 0) || (wvalid[b*Wc + kk - 1] > 0.5f);
        float s = -3.4e38f;
        if (valid) {
            const float* krow = qkv + (size_t)(b*LW + kk) * H3 + Hc + h*HDc;
            float acc = 0.f;
            #pragma unroll 8
            for (int d = 0; d < HDc; d += 4) {
                float4 kv = *(const float4*)&krow[d];
                acc += sq[d]*kv.x + sq[d+1]*kv.y + sq[d+2]*kv.z + sq[d+3]*kv.w;
            }
            s = acc * scale;
        }
        sc[kk] = s;
    }
    __syncthreads();

    float mx = -3.4e38f;
    for (int kk = tid; kk < LW; kk += 128) mx = fmaxf(mx, sc[kk]);
    red[tid] = mx; __syncthreads();
    for (int o = 64; o > 0; o >>= 1) { if (tid < o) red[tid] = fmaxf(red[tid], red[tid+o]); __syncthreads(); }
    mx = red[0];
    __syncthreads();

    float ssum = 0.f;
    for (int kk = tid; kk < LW; kk += 128) {
        float s = sc[kk];
        float e = (s <= -1e37f) ? 0.f : expf(s - mx);
        sc[kk] = e; ssum += e;
    }
    red[tid] = ssum; __syncthreads();
    for (int o = 64; o > 0; o >>= 1) { if (tid < o) red[tid] += red[tid+o]; __syncthreads(); }
    float inv = 1.f / red[0];

    float* crow = ctx + (size_t)(b*LW + qi) * Hc + h*HDc;
    const float* vbase = qkv + (size_t)(b*LW) * H3 + 2*Hc + h*HDc;
    for (int d = tid; d < HDc; d += 128) {
        float acc = 0.f;
        for (int kk = 0; kk < LW; kk++)
            acc += sc[kk] * vbase[(size_t)kk*H3 + d];
        crow[d] = acc * inv;
    }
}

// ---------------- layernorm over H=768 per row ------------------------------
__global__ void ln_kernel(const float* __restrict__ y,
                          const float* __restrict__ s,
                          const float* __restrict__ bi,
                          float* __restrict__ x) {
    int row = blockIdx.x;
    int tid = threadIdx.x; // 256
    __shared__ float red[256];
    const float* yr = y + (size_t)row * Hc;
    float v0 = yr[tid], v1 = yr[tid+256], v2 = yr[tid+512];
    red[tid] = v0 + v1 + v2; __syncthreads();
    for (int o = 128; o > 0; o >>= 1) { if (tid < o) red[tid] += red[tid+o]; __syncthreads(); }
    float mean = red[0] * (1.f/768.f);
    __syncthreads();
    float d0 = v0-mean, d1 = v1-mean, d2 = v2-mean;
    red[tid] = d0*d0 + d1*d1 + d2*d2; __syncthreads();
    for (int o = 128; o > 0; o >>= 1) { if (tid < o) red[tid] += red[tid+o]; __syncthreads(); }
    float inv = rsqrtf(red[0] * (1.f/768.f) + 1e-5f);
    float* xr = x + (size_t)row * Hc;
    xr[tid]     = d0*inv*s[tid]     + bi[tid];
    xr[tid+256] = d1*inv*s[tid+256] + bi[tid+256];
    xr[tid+512] = d2*inv*s[tid+512] + bi[tid+512];
}

// ---------------- classifier + pooled copy ----------------------------------
__global__ void cls_kernel(const float* __restrict__ x,
                           const float* __restrict__ cw,
                           const float* __restrict__ cb,
                           float* __restrict__ out) {
    int b = blockIdx.x;
    int tid = threadIdx.x; // 256
    __shared__ float red[256];
    const float* row = x + (size_t)(b*LW) * Hc;
    // pooled section follows logits section
    out[Bc*NLABc + b*Hc + tid]     = row[tid];
    out[Bc*NLABc + b*Hc + tid+256] = row[tid+256];
    out[Bc*NLABc + b*Hc + tid+512] = row[tid+512];
    for (int lab = 0; lab < NLABc; lab++) {
        const float* wr = cw + lab*Hc;
        float s = row[tid]*wr[tid] + row[tid+256]*wr[tid+256] + row[tid+512]*wr[tid+512];
        red[tid] = s; __syncthreads();
        for (int o = 128; o > 0; o >>= 1) { if (tid < o) red[tid] += red[tid+o]; __syncthreads(); }
        if (tid == 0) out[b*NLABc + lab] = red[0] + cb[lab];
        __syncthreads();
    }
}

// ---------------- launch -----------------------------------------------------
extern "C" void kernel_launch(void* const* d_in, const int* in_sizes, int n_in,
                              void* d_out, int out_size) {
    (void)in_sizes; (void)n_in; (void)out_size;
    const float* hidden = (const float*)d_in[0];
    const int*   widx   = (const int*)  d_in[1];
    const void*  gmask  = d_in[2];
    const void*  wvin   = d_in[3];
    const float* qkv_w  = (const float*)d_in[4];
    const float* qkv_b  = (const float*)d_in[5];
    const float* out_w  = (const float*)d_in[6];
    const float* out_b  = (const float*)d_in[7];
    const float* ff1_w  = (const float*)d_in[8];
    const float* ff1_b  = (const float*)d_in[9];
    const float* ff2_w  = (const float*)d_in[10];
    const float* ff2_b  = (const float*)d_in[11];
    const float* ln1_s  = (const float*)d_in[12];
    const float* ln1_b  = (const float*)d_in[13];
    const float* ln2_s  = (const float*)d_in[14];
    const float* ln2_b  = (const float*)d_in[15];
    const float* cls_w  = (const float*)d_in[16];
    const float* cls_b  = (const float*)d_in[17];
    float* out = (float*)d_out;

    float *x, *qkv, *ctx, *y, *ffh, *wval;
    cudaGetSymbolAddress((void**)&x,    g_x);
    cudaGetSymbolAddress((void**)&qkv,  g_qkv);
    cudaGetSymbolAddress((void**)&ctx,  g_ctx);
    cudaGetSymbolAddress((void**)&y,    g_y);
    cudaGetSymbolAddress((void**)&ffh,  g_ffh);
    cudaGetSymbolAddress((void**)&wval, g_wvalid);

    detect_kernel<<<1, 256>>>((const unsigned int*)gmask, (const unsigned int*)wvin);
    build_kernel<<<dim3(LW, Bc), 256>>>(hidden, widx, gmask, wvin, x, wval);

    const int MB = (MROWS + 127) / 128;  // 33
    for (int l = 0; l < NLc; l++) {
        sgemm_kernel<0><<<dim3(H3/128, MB), 256>>>(
            x, qkv_w + (size_t)l*H3*Hc, qkv_b + (size_t)l*H3, nullptr, qkv,
            MROWS, H3, Hc);
        attn_kernel<<<dim3(LW, NHc, Bc), 128>>>(qkv, wval, ctx);
        sgemm_kernel<2><<<dim3(Hc/128, MB), 256>>>(
            ctx, out_w + (size_t)l*Hc*Hc, out_b + (size_t)l*Hc, x, y,
            MROWS, Hc, Hc);
        ln_kernel<<<MROWS, 256>>>(y, ln1_s + (size_t)l*Hc, ln1_b + (size_t)l*Hc, x);
        sgemm_kernel<1><<<dim3(FFc/128, MB), 256>>>(
            x, ff1_w + (size_t)l*FFc*Hc, ff1_b + (size_t)l*FFc, nullptr, ffh,
            MROWS, FFc, Hc);
        sgemm_kernel<2><<<dim3(Hc/128, MB), 256>>>(
            ffh, ff2_w + (size_t)l*Hc*FFc, ff2_b + (size_t)l*Hc, x, y,
            MROWS, Hc, FFc);
        ln_kernel<<<MROWS, 256>>>(y, ln2_s + (size_t)l*Hc, ln2_b + (size_t)l*Hc, x);
    }
    cls_kernel<<<Bc, 256>>>(x, cls_w, cls_b, out);
}

// round 5
// speedup vs baseline: 2.1320x; 2.1320x over previous
#include <cuda_runtime.h>
#include <cuda_bf16.h>
#include <cstdint>
#include <math.h>

#define Bc    32
#define Sc    512
#define Hc    768
#define Wc    128
#define Gc    4
#define NHc   4
#define HDc   192
#define FFc   2048
#define NLc   2
#define NLABc 6
#define LW    129
#define MROWS (Bc*LW)     /* 4128 */
#define H3    (3*Hc)      /* 2304 */

// ---------------- scratch (device globals; no allocation allowed) ----------
__device__ float g_x  [MROWS*Hc];
__device__ float g_qkv[MROWS*H3];
__device__ float g_ctx[MROWS*Hc];
__device__ float g_y  [MROWS*Hc];
__device__ float g_ffh[MROWS*FFc];
__device__ float g_wvalid[Bc*Wc];
__device__ int   g_mtype;
__device__ int   g_vtype;

// ---------------- helpers ---------------------------------------------------
__device__ __forceinline__ uint32_t smem_u32(const void* p){
    uint32_t a;
    asm("{ .reg .u64 t; cvta.to.shared.u64 t, %1; cvt.u32.u64 %0, t; }" : "=r"(a) : "l"(p));
    return a;
}
__device__ __forceinline__ void ldsm4(uint32_t* r, uint32_t addr){
    asm volatile("ldmatrix.sync.aligned.m8n8.x4.shared.b16 {%0,%1,%2,%3}, [%4];"
        : "=r"(r[0]), "=r"(r[1]), "=r"(r[2]), "=r"(r[3]) : "r"(addr));
}
__device__ __forceinline__ void mma16816(float* c, const uint32_t* a, uint32_t b0, uint32_t b1){
    asm volatile("mma.sync.aligned.m16n8k16.row.col.f32.bf16.bf16.f32 "
        "{%0,%1,%2,%3}, {%4,%5,%6,%7}, {%8,%9}, {%0,%1,%2,%3};"
        : "+f"(c[0]), "+f"(c[1]), "+f"(c[2]), "+f"(c[3])
        : "r"(a[0]), "r"(a[1]), "r"(a[2]), "r"(a[3]), "r"(b0), "r"(b1));
}

// ---------------- dtype detection for bool inputs --------------------------
__global__ void detect_kernel(const unsigned int* __restrict__ gm,
                              const unsigned int* __restrict__ wv) {
    __shared__ int fm, bm_, fv, bv;
    int tid = threadIdx.x;
    if (tid == 0) { fm = 0; bm_ = 0; fv = 0; bv = 0; }
    __syncthreads();
    for (int i = tid; i < 4096; i += 256) {
        unsigned v = gm[i];
        if (v == 0x3f800000u) atomicOr(&fm, 1);
        else if (v > 1u)      atomicOr(&bm_, 1);
    }
    for (int i = tid; i < 1024; i += 256) {
        unsigned v = wv[i];
        if (v == 0x3f800000u) atomicOr(&fv, 1);
        else if (v > 1u)      atomicOr(&bv, 1);
    }
    __syncthreads();
    if (tid == 0) {
        g_mtype = fm ? 0 : (bm_ ? 1 : 2);
        g_vtype = fv ? 0 : (bv ? 1 : 2);
    }
}

__device__ __forceinline__ float read_flag(const void* p, int t, int i) {
    if (t == 0) return ((const float*)p)[i];
    if (t == 1) return (float)((const unsigned char*)p)[i];
    return (float)((const int*)p)[i];
}

// ---------------- build x = [cls ; word embeddings], wvalid -----------------
__global__ void build_kernel(const float* __restrict__ hidden,
                             const int*   __restrict__ widx,
                             const void*  __restrict__ gmask,
                             const void*  __restrict__ wvin,
                             float* __restrict__ x,
                             float* __restrict__ wvalid) {
    int qi  = blockIdx.x;
    int b   = blockIdx.y;
    int tid = threadIdx.x;
    float* xr = x + ((size_t)(b*LW) + qi) * Hc;
    if (qi == 0) {
        const float* hr = hidden + (size_t)b * Sc * Hc;
        xr[tid] = hr[tid]; xr[tid+256] = hr[tid+256]; xr[tid+512] = hr[tid+512];
        return;
    }
    int w = qi - 1;
    int mt = g_mtype, vt = g_vtype;
    int base = (b*Wc + w) * Gc;
    float mk0 = read_flag(gmask, mt, base+0);
    float mk1 = read_flag(gmask, mt, base+1);
    float mk2 = read_flag(gmask, mt, base+2);
    float mk3 = read_flag(gmask, mt, base+3);
    float cnt = mk0 + mk1 + mk2 + mk3;
    float valid = read_flag(wvin, vt, b*Wc + w);
    if (tid == 0) wvalid[b*Wc + w] = valid;
    float invc = valid / fmaxf(cnt, 1.f);
    const float* hb = hidden + (size_t)b * Sc * Hc;
    const float* r0 = hb + (size_t)widx[base+0] * Hc;
    const float* r1 = hb + (size_t)widx[base+1] * Hc;
    const float* r2 = hb + (size_t)widx[base+2] * Hc;
    const float* r3 = hb + (size_t)widx[base+3] * Hc;
    for (int d = tid; d < Hc; d += 256) {
        float acc = mk0*r0[d] + mk1*r1[d] + mk2*r2[d] + mk3*r3[d];
        xr[d] = acc * invc;
    }
}

// ---------------- split-bf16 mma.sync GEMM ----------------------------------
// C[M,N] = A[M,K] @ Wt[N,K]^T + bias (+res/relu). A,B -> hi/lo bf16;
// acc += Ah*Bh + Ah*Bl + Al*Bh (fp32 accumulate) => ~fp32 precision.
// CTA tile 128x128, BK=32, 8 warps (4m x 2n), warp tile 32x64.
#define ROWB 80                 /* bytes per smem row: 32 bf16 + 8 pad */
#define MATB (128*ROWB)         /* 10240 B per matrix */
#define STAGEB (4*MATB)         /* Ah,Al,Bh,Bl */
#define GEMM_SMEM (2*STAGEB)    /* 81920 B */

__device__ __forceinline__ void cvt_store(char* hi, char* lo, uint32_t o, float4 v){
    __nv_bfloat162 h0 = __floats2bfloat162_rn(v.x, v.y);
    __nv_bfloat162 h1 = __floats2bfloat162_rn(v.z, v.w);
    float lx = v.x - __bfloat162float(h0.x);
    float ly = v.y - __bfloat162float(h0.y);
    float lz = v.z - __bfloat162float(h1.x);
    float lw = v.w - __bfloat162float(h1.y);
    __nv_bfloat162 l0 = __floats2bfloat162_rn(lx, ly);
    __nv_bfloat162 l1 = __floats2bfloat162_rn(lz, lw);
    *(uint2*)(hi + o) = make_uint2(*(uint32_t*)&h0, *(uint32_t*)&h1);
    *(uint2*)(lo + o) = make_uint2(*(uint32_t*)&l0, *(uint32_t*)&l1);
}

template<int EPI>  // 0=bias, 1=bias+relu, 2=bias+residual
__global__ __launch_bounds__(256, 1) void hgemm_kernel(
        const float* __restrict__ A, const float* __restrict__ Wt,
        const float* __restrict__ bias, const float* __restrict__ res,
        float* __restrict__ C, int M_, int N_, int K_) {
    extern __shared__ char smc[];
    const uint32_t sb = smem_u32(smc);
    const int tid = threadIdx.x, wid = tid >> 5, lane = tid & 31;
    const int bm = blockIdx.y * 128, bn = blockIdx.x * 128;
    const int wm = (wid & 3) * 32, wn = (wid >> 2) * 64;

    // global load assignment: row r = tid>>1 (0..127), 16 cols starting cb
    const int r  = tid >> 1;
    const int cb = (tid & 1) << 4;
    const bool aok = (bm + r) < M_;
    const float* Ap = A  + (size_t)(bm + r) * K_ + cb;
    const float* Bp = Wt + (size_t)(bn + r) * K_ + cb;

    float4 ra[4], rb[4];
    const int KT = K_ >> 5;

#define LOADG(kt) do { \
    const float* _ap = Ap + (kt)*32; \
    const float* _bp = Bp + (kt)*32; \
    _Pragma("unroll") \
    for (int u = 0; u < 4; u++) { \
        ra[u] = aok ? *(const float4*)(_ap + u*4) : make_float4(0.f,0.f,0.f,0.f); \
        rb[u] = *(const float4*)(_bp + u*4); \
    } } while(0)

#define CVTST(st) do { \
    char* _b = smc + (st)*STAGEB; \
    uint32_t _o = (uint32_t)r*ROWB + (uint32_t)cb*2u; \
    _Pragma("unroll") \
    for (int u = 0; u < 4; u++) { \
        cvt_store(_b,          _b + MATB,   _o + u*8u, ra[u]); \
        cvt_store(_b + 2*MATB, _b + 3*MATB, _o + u*8u, rb[u]); \
    } } while(0)

    float acc[2][8][4];
    #pragma unroll
    for (int i = 0; i < 2; i++)
        #pragma unroll
        for (int j = 0; j < 8; j++)
            #pragma unroll
            for (int q = 0; q < 4; q++) acc[i][j][q] = 0.f;

    const uint32_t aoff = (uint32_t)(lane & 15) * ROWB + (uint32_t)(lane >> 4) * 16u;

    LOADG(0);
    CVTST(0);
    if (KT > 1) LOADG(1);
    __syncthreads();

    for (int kt = 0; kt < KT; kt++) {
        const int cur = kt & 1;
        if (kt + 1 < KT) {
            CVTST(1 - cur);
            if (kt + 2 < KT) LOADG(kt + 2);
        }
        const uint32_t SA = sb + (uint32_t)cur * STAGEB;
        const uint32_t SAh = SA, SAl = SA + MATB, SBh = SA + 2*MATB, SBl = SA + 3*MATB;
        #pragma unroll
        for (int k16 = 0; k16 < 32; k16 += 16) {
            uint32_t ah[2][4], al[2][4];
            ldsm4(ah[0], SAh + (uint32_t)(wm     )*ROWB + aoff + k16*2u);
            ldsm4(ah[1], SAh + (uint32_t)(wm + 16)*ROWB + aoff + k16*2u);
            ldsm4(al[0], SAl + (uint32_t)(wm     )*ROWB + aoff + k16*2u);
            ldsm4(al[1], SAl + (uint32_t)(wm + 16)*ROWB + aoff + k16*2u);
            #pragma unroll
            for (int nf = 0; nf < 4; nf++) {
                uint32_t bh[4], bl[4];
                ldsm4(bh, SBh + (uint32_t)(wn + nf*16)*ROWB + aoff + k16*2u);
                ldsm4(bl, SBl + (uint32_t)(wn + nf*16)*ROWB + aoff + k16*2u);
                #pragma unroll
                for (int mf = 0; mf < 2; mf++) {
                    mma16816(acc[mf][nf*2+0], ah[mf], bh[0], bh[2]);
                    mma16816(acc[mf][nf*2+1], ah[mf], bh[1], bh[3]);
                    mma16816(acc[mf][nf*2+0], ah[mf], bl[0], bl[2]);
                    mma16816(acc[mf][nf*2+1], ah[mf], bl[1], bl[3]);
                    mma16816(acc[mf][nf*2+0], al[mf], bh[0], bh[2]);
                    mma16816(acc[mf][nf*2+1], al[mf], bh[1], bh[3]);
                }
            }
        }
        __syncthreads();
    }

    // epilogue
    #pragma unroll
    for (int mf = 0; mf < 2; mf++) {
        #pragma unroll
        for (int nf = 0; nf < 8; nf++) {
            const int row0 = bm + wm + mf*16 + (lane >> 2);
            const int col  = bn + wn + nf*8 + ((lane & 3) << 1);
            float2 b2 = *(const float2*)(bias + col);
            if (row0 < M_) {
                float2 v = make_float2(acc[mf][nf][0] + b2.x, acc[mf][nf][1] + b2.y);
                if (EPI == 2) {
                    float2 rr = *(const float2*)(res + (size_t)row0 * N_ + col);
                    v.x += rr.x; v.y += rr.y;
                }
                if (EPI == 1) { v.x = fmaxf(v.x, 0.f); v.y = fmaxf(v.y, 0.f); }
                *(float2*)(C + (size_t)row0 * N_ + col) = v;
            }
            const int row1 = row0 + 8;
            if (row1 < M_) {
                float2 v = make_float2(acc[mf][nf][2] + b2.x, acc[mf][nf][3] + b2.y);
                if (EPI == 2) {
                    float2 rr = *(const float2*)(res + (size_t)row1 * N_ + col);
                    v.x += rr.x; v.y += rr.y;
                }
                if (EPI == 1) { v.x = fmaxf(v.x, 0.f); v.y = fmaxf(v.y, 0.f); }
                *(float2*)(C + (size_t)row1 * N_ + col) = v;
            }
        }
    }
#undef LOADG
#undef CVTST
}

// ---------------- attention: one block per (b, h), K/V in smem --------------
#define PADK 193
#define ATTN_SMEM ((2*LW*PADK + 8*768 + 132) * 4)

__global__ __launch_bounds__(256, 1) void attn_kernel(
        const float* __restrict__ qkv,
        const float* __restrict__ wvalid,
        float* __restrict__ ctx) {
    const int h = blockIdx.x, b = blockIdx.y;
    extern __shared__ float sm[];
    float* Ks   = sm;
    float* Vs   = Ks + LW * PADK;
    float* sq   = Vs + LW * PADK;
    float* madd = sq + 8 * 768;
    const int tid = threadIdx.x, w = tid >> 5, lane = tid & 31;

    const float* base = qkv + (size_t)(b * LW) * H3 + h * HDc;
    for (int idx = tid; idx < LW * HDc; idx += 256) {
        int rr = idx / HDc, c = idx - rr * HDc;
        Ks[rr * PADK + c] = base[(size_t)rr * H3 + Hc + c];
        Vs[rr * PADK + c] = base[(size_t)rr * H3 + 2*Hc + c];
    }
    for (int kk = tid; kk < LW; kk += 256)
        madd[kk] = (kk == 0 || wvalid[b * Wc + kk - 1] > 0.5f) ? 0.f : -3.0e38f;
    __syncthreads();

    const float scale = 0.07216878364870323f; // 1/sqrt(192)
    float* myq = sq + w * 768;

    for (int q0 = w * 4; q0 < LW; q0 += 32) {
        const int nq = (LW - q0 < 4) ? (LW - q0) : 4;
        #pragma unroll
        for (int t = 0; t < 4; t++) {
            if (t < nq) {
                const float* qr = qkv + (size_t)(b * LW + q0 + t) * H3 + h * HDc;
                for (int j = lane; j < HDc; j += 32) myq[t * 192 + j] = qr[j];
            } else {
                for (int j = lane; j < HDc; j += 32) myq[t * 192 + j] = 0.f;
            }
        }
        __syncwarp();

        float s[4][4];
        #pragma unroll
        for (int t = 0; t < 4; t++)
            #pragma unroll
            for (int i = 0; i < 4; i++) s[t][i] = 0.f;

        #pragma unroll 4
        for (int d = 0; d < HDc; d++) {
            float q0v = myq[0*192 + d], q1v = myq[1*192 + d];
            float q2v = myq[2*192 + d], q3v = myq[3*192 + d];
            float k0 = Ks[(lane     ) * PADK + d];
            float k1 = Ks[(lane + 32) * PADK + d];
            float k2 = Ks[(lane + 64) * PADK + d];
            float k3 = Ks[(lane + 96) * PADK + d];
            s[0][0] += q0v*k0; s[0][1] += q0v*k1; s[0][2] += q0v*k2; s[0][3] += q0v*k3;
            s[1][0] += q1v*k0; s[1][1] += q1v*k1; s[1][2] += q1v*k2; s[1][3] += q1v*k3;
            s[2][0] += q2v*k0; s[2][1] += q2v*k1; s[2][2] += q2v*k2; s[2][3] += q2v*k3;
            s[3][0] += q3v*k0; s[3][1] += q3v*k1; s[3][2] += q3v*k2; s[3][3] += q3v*k3;
        }

        float s128[4];
        #pragma unroll
        for (int t = 0; t < 4; t++) {
            float p = 0.f;
            #pragma unroll
            for (int j = 0; j < 6; j++)
                p += myq[t*192 + lane + 32*j] * Ks[128 * PADK + lane + 32*j];
            #pragma unroll
            for (int o = 16; o > 0; o >>= 1) p += __shfl_xor_sync(0xffffffffu, p, o);
            s128[t] = p;
        }

        const float m0 = madd[lane], m1 = madd[lane+32], m2 = madd[lane+64], m3 = madd[lane+96];
        const float m128 = madd[128];
        float e[4][4], e128[4], inv[4];
        #pragma unroll
        for (int t = 0; t < 4; t++) {
            s[t][0] = s[t][0]*scale + m0;
            s[t][1] = s[t][1]*scale + m1;
            s[t][2] = s[t][2]*scale + m2;
            s[t][3] = s[t][3]*scale + m3;
            s128[t] = s128[t]*scale + m128;
            float mm = fmaxf(fmaxf(s[t][0], s[t][1]), fmaxf(s[t][2], s[t][3]));
            #pragma unroll
            for (int o = 16; o > 0; o >>= 1) mm = fmaxf(mm, __shfl_xor_sync(0xffffffffu, mm, o));
            mm = fmaxf(mm, s128[t]);
            e[t][0] = expf(s[t][0] - mm); e[t][1] = expf(s[t][1] - mm);
            e[t][2] = expf(s[t][2] - mm); e[t][3] = expf(s[t][3] - mm);
            float ss = e[t][0] + e[t][1] + e[t][2] + e[t][3];
            #pragma unroll
            for (int o = 16; o > 0; o >>= 1) ss += __shfl_xor_sync(0xffffffffu, ss, o);
            e128[t] = expf(s128[t] - mm);
            ss += e128[t];
            inv[t] = 1.f / ss;
        }
        __syncwarp();
        #pragma unroll
        for (int t = 0; t < 4; t++) {
            myq[t*192 + lane     ] = e[t][0];
            myq[t*192 + lane + 32] = e[t][1];
            myq[t*192 + lane + 64] = e[t][2];
            myq[t*192 + lane + 96] = e[t][3];
            if (lane == 0) myq[t*192 + 128] = e128[t];
        }
        __syncwarp();

        float acc[4][6];
        #pragma unroll
        for (int t = 0; t < 4; t++)
            #pragma unroll
            for (int j = 0; j < 6; j++) acc[t][j] = 0.f;
        #pragma unroll 2
        for (int kk = 0; kk < LW; kk++) {
            float p0 = myq[0*192 + kk], p1 = myq[1*192 + kk];
            float p2 = myq[2*192 + kk], p3 = myq[3*192 + kk];
            #pragma unroll
            for (int j = 0; j < 6; j++) {
                float v = Vs[kk * PADK + lane + 32*j];
                acc[0][j] += p0 * v; acc[1][j] += p1 * v;
                acc[2][j] += p2 * v; acc[3][j] += p3 * v;
            }
        }
        for (int t = 0; t < nq; t++) {
            float* crow = ctx + (size_t)(b * LW + q0 + t) * Hc + h * HDc;
            #pragma unroll
            for (int j = 0; j < 6; j++)
                crow[lane + 32*j] = acc[t][j] * inv[t];
        }
        __syncwarp();
    }
}

// ---------------- layernorm over H=768 per row ------------------------------
__global__ void ln_kernel(const float* __restrict__ y,
                          const float* __restrict__ s,
                          const float* __restrict__ bi,
                          float* __restrict__ x) {
    int row = blockIdx.x;
    int tid = threadIdx.x;
    __shared__ float red[256];
    const float* yr = y + (size_t)row * Hc;
    float v0 = yr[tid], v1 = yr[tid+256], v2 = yr[tid+512];
    red[tid] = v0 + v1 + v2; __syncthreads();
    for (int o = 128; o > 0; o >>= 1) { if (tid < o) red[tid] += red[tid+o]; __syncthreads(); }
    float mean = red[0] * (1.f/768.f);
    __syncthreads();
    float d0 = v0-mean, d1 = v1-mean, d2 = v2-mean;
    red[tid] = d0*d0 + d1*d1 + d2*d2; __syncthreads();
    for (int o = 128; o > 0; o >>= 1) { if (tid < o) red[tid] += red[tid+o]; __syncthreads(); }
    float inv = rsqrtf(red[0] * (1.f/768.f) + 1e-5f);
    float* xr = x + (size_t)row * Hc;
    xr[tid]     = d0*inv*s[tid]     + bi[tid];
    xr[tid+256] = d1*inv*s[tid+256] + bi[tid+256];
    xr[tid+512] = d2*inv*s[tid+512] + bi[tid+512];
}

// ---------------- classifier + pooled copy ----------------------------------
__global__ void cls_kernel(const float* __restrict__ x,
                           const float* __restrict__ cw,
                           const float* __restrict__ cb,
                           float* __restrict__ out) {
    int b = blockIdx.x;
    int tid = threadIdx.x;
    __shared__ float red[256];
    const float* row = x + (size_t)(b*LW) * Hc;
    out[Bc*NLABc + b*Hc + tid]     = row[tid];
    out[Bc*NLABc + b*Hc + tid+256] = row[tid+256];
    out[Bc*NLABc + b*Hc + tid+512] = row[tid+512];
    for (int lab = 0; lab < NLABc; lab++) {
        const float* wr = cw + lab*Hc;
        float s = row[tid]*wr[tid] + row[tid+256]*wr[tid+256] + row[tid+512]*wr[tid+512];
        red[tid] = s; __syncthreads();
        for (int o = 128; o > 0; o >>= 1) { if (tid < o) red[tid] += red[tid+o]; __syncthreads(); }
        if (tid == 0) out[b*NLABc + lab] = red[0] + cb[lab];
        __syncthreads();
    }
}

// ---------------- launch -----------------------------------------------------
extern "C" void kernel_launch(void* const* d_in, const int* in_sizes, int n_in,
                              void* d_out, int out_size) {
    (void)in_sizes; (void)n_in; (void)out_size;
    const float* hidden = (const float*)d_in[0];
    const int*   widx   = (const int*)  d_in[1];
    const void*  gmask  = d_in[2];
    const void*  wvin   = d_in[3];
    const float* qkv_w  = (const float*)d_in[4];
    const float* qkv_b  = (const float*)d_in[5];
    const float* out_w  = (const float*)d_in[6];
    const float* out_b  = (const float*)d_in[7];
    const float* ff1_w  = (const float*)d_in[8];
    const float* ff1_b  = (const float*)d_in[9];
    const float* ff2_w  = (const float*)d_in[10];
    const float* ff2_b  = (const float*)d_in[11];
    const float* ln1_s  = (const float*)d_in[12];
    const float* ln1_b  = (const float*)d_in[13];
    const float* ln2_s  = (const float*)d_in[14];
    const float* ln2_b  = (const float*)d_in[15];
    const float* cls_w  = (const float*)d_in[16];
    const float* cls_b  = (const float*)d_in[17];
    float* out = (float*)d_out;

    float *x, *qkv, *ctx, *y, *ffh, *wval;
    cudaGetSymbolAddress((void**)&x,    g_x);
    cudaGetSymbolAddress((void**)&qkv,  g_qkv);
    cudaGetSymbolAddress((void**)&ctx,  g_ctx);
    cudaGetSymbolAddress((void**)&y,    g_y);
    cudaGetSymbolAddress((void**)&ffh,  g_ffh);
    cudaGetSymbolAddress((void**)&wval, g_wvalid);

    cudaFuncSetAttribute(hgemm_kernel<0>, cudaFuncAttributeMaxDynamicSharedMemorySize, (int)GEMM_SMEM);
    cudaFuncSetAttribute(hgemm_kernel<1>, cudaFuncAttributeMaxDynamicSharedMemorySize, (int)GEMM_SMEM);
    cudaFuncSetAttribute(hgemm_kernel<2>, cudaFuncAttributeMaxDynamicSharedMemorySize, (int)GEMM_SMEM);
    cudaFuncSetAttribute(attn_kernel,     cudaFuncAttributeMaxDynamicSharedMemorySize, (int)ATTN_SMEM);

    detect_kernel<<<1, 256>>>((const unsigned int*)gmask, (const unsigned int*)wvin);
    build_kernel<<<dim3(LW, Bc), 256>>>(hidden, widx, gmask, wvin, x, wval);

    const int MB = (MROWS + 127) / 128;  // 33
    for (int l = 0; l < NLc; l++) {
        hgemm_kernel<0><<<dim3(H3/128, MB), 256, GEMM_SMEM>>>(
            x, qkv_w + (size_t)l*H3*Hc, qkv_b + (size_t)l*H3, nullptr, qkv,
            MROWS, H3, Hc);
        attn_kernel<<<dim3(NHc, Bc), 256, ATTN_SMEM>>>(qkv, wval, ctx);
        hgemm_kernel<2><<<dim3(Hc/128, MB), 256, GEMM_SMEM>>>(
            ctx, out_w + (size_t)l*Hc*Hc, out_b + (size_t)l*Hc, x, y,
            MROWS, Hc, Hc);
        ln_kernel<<<MROWS, 256>>>(y, ln1_s + (size_t)l*Hc, ln1_b + (size_t)l*Hc, x);
        hgemm_kernel<1><<<dim3(FFc/128, MB), 256, GEMM_SMEM>>>(
            x, ff1_w + (size_t)l*FFc*Hc, ff1_b + (size_t)l*FFc, nullptr, ffh,
            MROWS, FFc, Hc);
        hgemm_kernel<2><<<dim3(Hc/128, MB), 256, GEMM_SMEM>>>(
            ffh, ff2_w + (size_t)l*Hc*FFc, ff2_b + (size_t)l*Hc, x, y,
            MROWS, Hc, FFc);
        ln_kernel<<<MROWS, 256>>>(y, ln2_s + (size_t)l*Hc, ln2_b + (size_t)l*Hc, x);
    }
    cls_kernel<<<Bc, 256>>>(x, cls_w, cls_b, out);
}

// round 7
// speedup vs baseline: 2.1967x; 1.0304x over previous
#include <cuda_runtime.h>
#include <cuda_bf16.h>
#include <cstdint>
#include <math.h>

#define Bc    32
#define Sc    512
#define Hc    768
#define Wc    128
#define Gc    4
#define NHc   4
#define HDc   192
#define FFc   2048
#define NLc   2
#define NLABc 6
#define LW    129
#define MROWS (Bc*LW)     /* 4128 */
#define H3    (3*Hc)      /* 2304 */

// weight hi/lo pool offsets (elements)
#define OFF_QKV 0
#define SZ_QKV (NLc*H3*Hc)
#define OFF_OUT (OFF_QKV + SZ_QKV)
#define SZ_OUT (NLc*Hc*Hc)
#define OFF_FF1 (OFF_OUT + SZ_OUT)
#define SZ_FF1 (NLc*FFc*Hc)
#define OFF_FF2 (OFF_FF1 + SZ_FF1)
#define SZ_FF2 (NLc*Hc*FFc)
#define WTOT (OFF_FF2 + SZ_FF2)   /* 11,010,048 */

// ---------------- scratch (device globals; no allocation allowed) ----------
__device__ float g_x  [MROWS*Hc];
__device__ float g_qkv[MROWS*H3];
__device__ float g_y  [MROWS*Hc];
__device__ float g_wvalid[Bc*Wc];
__device__ int   g_mtype;
__device__ int   g_vtype;
__device__ __nv_bfloat16 g_wh[WTOT];
__device__ __nv_bfloat16 g_wl[WTOT];
__device__ __nv_bfloat16 g_xh[MROWS*Hc],  g_xl[MROWS*Hc];
__device__ __nv_bfloat16 g_cth[MROWS*Hc], g_ctl[MROWS*Hc];
__device__ __nv_bfloat16 g_fh[MROWS*FFc], g_fl[MROWS*FFc];

// ---------------- helpers ---------------------------------------------------
__device__ __forceinline__ uint32_t smem_u32(const void* p){
    uint32_t a;
    asm("{ .reg .u64 t; cvta.to.shared.u64 t, %1; cvt.u32.u64 %0, t; }" : "=r"(a) : "l"(p));
    return a;
}
__device__ __forceinline__ void ldsm4(uint32_t* r, uint32_t addr){
    asm volatile("ldmatrix.sync.aligned.m8n8.x4.shared.b16 {%0,%1,%2,%3}, [%4];"
        : "=r"(r[0]), "=r"(r[1]), "=r"(r[2]), "=r"(r[3]) : "r"(addr));
}
__device__ __forceinline__ void mma16816(float* c, const uint32_t* a, uint32_t b0, uint32_t b1){
    asm volatile("mma.sync.aligned.m16n8k16.row.col.f32.bf16.bf16.f32 "
        "{%0,%1,%2,%3}, {%4,%5,%6,%7}, {%8,%9}, {%0,%1,%2,%3};"
        : "+f"(c[0]), "+f"(c[1]), "+f"(c[2]), "+f"(c[3])
        : "r"(a[0]), "r"(a[1]), "r"(a[2]), "r"(a[3]), "r"(b0), "r"(b1));
}
__device__ __forceinline__ void split1(float v, __nv_bfloat16* hp, __nv_bfloat16* lp){
    __nv_bfloat16 h = __float2bfloat16(v);
    *hp = h;
    *lp = __float2bfloat16(v - __bfloat162float(h));
}
__device__ __forceinline__ void split2(float2 v, __nv_bfloat16* hp, __nv_bfloat16* lp){
    __nv_bfloat162 h = __floats2bfloat162_rn(v.x, v.y);
    __nv_bfloat162 l = __floats2bfloat162_rn(v.x - __bfloat162float(h.x),
                                             v.y - __bfloat162float(h.y));
    *(__nv_bfloat162*)hp = h;
    *(__nv_bfloat162*)lp = l;
}

// ---------------- weight conversion fp32 -> hi/lo bf16 ----------------------
__global__ void wconv_kernel(const float* __restrict__ src,
                             __nv_bfloat16* __restrict__ hi,
                             __nv_bfloat16* __restrict__ lo, int n){
    int i = (blockIdx.x * 256 + threadIdx.x) << 2;
    if (i >= n) return;
    float4 v = *(const float4*)(src + i);
    __nv_bfloat162 h0 = __floats2bfloat162_rn(v.x, v.y);
    __nv_bfloat162 h1 = __floats2bfloat162_rn(v.z, v.w);
    __nv_bfloat162 l0 = __floats2bfloat162_rn(v.x - __bfloat162float(h0.x),
                                              v.y - __bfloat162float(h0.y));
    __nv_bfloat162 l1 = __floats2bfloat162_rn(v.z - __bfloat162float(h1.x),
                                              v.w - __bfloat162float(h1.y));
    *(uint2*)(hi + i) = make_uint2(*(uint32_t*)&h0, *(uint32_t*)&h1);
    *(uint2*)(lo + i) = make_uint2(*(uint32_t*)&l0, *(uint32_t*)&l1);
}

// ---------------- dtype detection for bool inputs --------------------------
__global__ void detect_kernel(const unsigned int* __restrict__ gm,
                              const unsigned int* __restrict__ wv) {
    __shared__ int fm, bm_, fv, bv;
    int tid = threadIdx.x;
    if (tid == 0) { fm = 0; bm_ = 0; fv = 0; bv = 0; }
    __syncthreads();
    for (int i = tid; i < 4096; i += 256) {
        unsigned v = gm[i];
        if (v == 0x3f800000u) atomicOr(&fm, 1);
        else if (v > 1u)      atomicOr(&bm_, 1);
    }
    for (int i = tid; i < 1024; i += 256) {
        unsigned v = wv[i];
        if (v == 0x3f800000u) atomicOr(&fv, 1);
        else if (v > 1u)      atomicOr(&bv, 1);
    }
    __syncthreads();
    if (tid == 0) {
        g_mtype = fm ? 0 : (bm_ ? 1 : 2);
        g_vtype = fv ? 0 : (bv ? 1 : 2);
    }
}

__device__ __forceinline__ float read_flag(const void* p, int t, int i) {
    if (t == 0) return ((const float*)p)[i];
    if (t == 1) return (float)((const unsigned char*)p)[i];
    return (float)((const int*)p)[i];
}

// ---------------- build x = [cls ; word embeddings] + hi/lo -----------------
__global__ void build_kernel(const float* __restrict__ hidden,
                             const int*   __restrict__ widx,
                             const void*  __restrict__ gmask,
                             const void*  __restrict__ wvin,
                             float* __restrict__ x,
                             __nv_bfloat16* __restrict__ xh,
                             __nv_bfloat16* __restrict__ xl,
                             float* __restrict__ wvalid) {
    int qi  = blockIdx.x;
    int b   = blockIdx.y;
    int tid = threadIdx.x;
    size_t ro = ((size_t)(b*LW) + qi) * Hc;
    float* xr = x + ro;
    if (qi == 0) {
        const float* hr = hidden + (size_t)b * Sc * Hc;
        #pragma unroll
        for (int u = 0; u < 3; u++) {
            float v = hr[tid + 256*u];
            xr[tid + 256*u] = v;
            split1(v, xh + ro + tid + 256*u, xl + ro + tid + 256*u);
        }
        return;
    }
    int w = qi - 1;
    int mt = g_mtype, vt = g_vtype;
    int base = (b*Wc + w) * Gc;
    float mk0 = read_flag(gmask, mt, base+0);
    float mk1 = read_flag(gmask, mt, base+1);
    float mk2 = read_flag(gmask, mt, base+2);
    float mk3 = read_flag(gmask, mt, base+3);
    float cnt = mk0 + mk1 + mk2 + mk3;
    float valid = read_flag(wvin, vt, b*Wc + w);
    if (tid == 0) wvalid[b*Wc + w] = valid;
    float invc = valid / fmaxf(cnt, 1.f);
    const float* hb = hidden + (size_t)b * Sc * Hc;
    const float* r0 = hb + (size_t)widx[base+0] * Hc;
    const float* r1 = hb + (size_t)widx[base+1] * Hc;
    const float* r2 = hb + (size_t)widx[base+2] * Hc;
    const float* r3 = hb + (size_t)widx[base+3] * Hc;
    for (int d = tid; d < Hc; d += 256) {
        float acc = (mk0*r0[d] + mk1*r1[d] + mk2*r2[d] + mk3*r3[d]) * invc;
        xr[d] = acc;
        split1(acc, xh + ro + d, xl + ro + d);
    }
}

// ---------------- split-bf16 mma.sync GEMM (pre-split operands) -------------
// C[M,N] = (Ah+Al)[M,K] @ (Bh+Bl)[N,K]^T + bias (+res / relu)
// acc += Ah*Bh + Ah*Bl + Al*Bh. CTA 128x128, BK=32, 8 warps (4m x 2n).
#define ROWB 80
#define MATB (128*ROWB)          /* 10240 B per matrix-half */
#define STAGEB (4*MATB)          /* 40960: Ah,Al,Bh,Bl */
#define GEMM_SMEM (2*STAGEB)     /* 81920 */

template<int EPI>  // 0=bias->f32, 1=bias+relu->hi/lo, 2=bias+res->f32
__global__ __launch_bounds__(256, 1) void hgemm_kernel(
        const __nv_bfloat16* __restrict__ Ah, const __nv_bfloat16* __restrict__ Al,
        const __nv_bfloat16* __restrict__ Bh, const __nv_bfloat16* __restrict__ Bl,
        const float* __restrict__ bias, const float* __restrict__ res,
        float* __restrict__ C,
        __nv_bfloat16* __restrict__ Ch, __nv_bfloat16* __restrict__ Cl,
        int M_, int N_, int K_) {
    extern __shared__ char smc[];
    const uint32_t sb = smem_u32(smc);
    const int tid = threadIdx.x, wid = tid >> 5, lane = tid & 31;
    const int bm = blockIdx.y * 128, bn = blockIdx.x * 128;
    const int wm = (wid & 3) * 32, wn = (wid >> 2) * 64;

    const int r  = tid >> 1;
    const int cb = (tid & 1) << 4;   // 16 bf16 = 32B = 2x uint4
    const bool aok = (bm + r) < M_;
    const __nv_bfloat16* Ahp = Ah + (size_t)(bm + r) * K_ + cb;
    const __nv_bfloat16* Alp = Al + (size_t)(bm + r) * K_ + cb;
    const __nv_bfloat16* Bhp = Bh + (size_t)(bn + r) * K_ + cb;
    const __nv_bfloat16* Blp = Bl + (size_t)(bn + r) * K_ + cb;

    uint4 pa[2], pal[2], pb[2], pbl[2];
    const uint4 z4 = make_uint4(0u,0u,0u,0u);
    const int KT = K_ >> 5;

#define LOADG(kt) do { \
    _Pragma("unroll") \
    for (int u = 0; u < 2; u++) { \
        pa[u]  = aok ? *(const uint4*)(Ahp + (kt)*32 + u*8) : z4; \
        pal[u] = aok ? *(const uint4*)(Alp + (kt)*32 + u*8) : z4; \
        pb[u]  = *(const uint4*)(Bhp + (kt)*32 + u*8); \
        pbl[u] = *(const uint4*)(Blp + (kt)*32 + u*8); \
    } } while(0)

#define STST(st) do { \
    char* _b = smc + (st)*STAGEB; \
    uint32_t _o = (uint32_t)r*ROWB + (uint32_t)cb*2u; \
    _Pragma("unroll") \
    for (int u = 0; u < 2; u++) { \
        *(uint4*)(_b          + _o + u*16u) = pa[u]; \
        *(uint4*)(_b +   MATB + _o + u*16u) = pal[u]; \
        *(uint4*)(_b + 2*MATB + _o + u*16u) = pb[u]; \
        *(uint4*)(_b + 3*MATB + _o + u*16u) = pbl[u]; \
    } } while(0)

    float acc[2][8][4];
    #pragma unroll
    for (int i = 0; i < 2; i++)
        #pragma unroll
        for (int j = 0; j < 8; j++)
            #pragma unroll
            for (int q = 0; q < 4; q++) acc[i][j][q] = 0.f;

    const uint32_t aoff = (uint32_t)(lane & 15) * ROWB + (uint32_t)(lane >> 4) * 16u;

    LOADG(0);
    STST(0);
    if (KT > 1) LOADG(1);
    __syncthreads();

    for (int kt = 0; kt < KT; kt++) {
        const int cur = kt & 1;
        if (kt + 1 < KT) {
            STST(1 - cur);
            if (kt + 2 < KT) LOADG(kt + 2);
        }
        const uint32_t SA = sb + (uint32_t)cur * STAGEB;
        const uint32_t SAh = SA, SAl = SA + MATB, SBh = SA + 2*MATB, SBl = SA + 3*MATB;
        #pragma unroll
        for (int k16 = 0; k16 < 32; k16 += 16) {
            uint32_t ah[2][4], al[2][4];
            ldsm4(ah[0], SAh + (uint32_t)(wm     )*ROWB + aoff + k16*2u);
            ldsm4(ah[1], SAh + (uint32_t)(wm + 16)*ROWB + aoff + k16*2u);
            ldsm4(al[0], SAl + (uint32_t)(wm     )*ROWB + aoff + k16*2u);
            ldsm4(al[1], SAl + (uint32_t)(wm + 16)*ROWB + aoff + k16*2u);
            #pragma unroll
            for (int nf = 0; nf < 4; nf++) {
                uint32_t bh[4], bl[4];
                ldsm4(bh, SBh + (uint32_t)(wn + nf*16)*ROWB + aoff + k16*2u);
                ldsm4(bl, SBl + (uint32_t)(wn + nf*16)*ROWB + aoff + k16*2u);
                #pragma unroll
                for (int mf = 0; mf < 2; mf++) {
                    mma16816(acc[mf][nf*2+0], ah[mf], bh[0], bh[2]);
                    mma16816(acc[mf][nf*2+1], ah[mf], bh[1], bh[3]);
                    mma16816(acc[mf][nf*2+0], ah[mf], bl[0], bl[2]);
                    mma16816(acc[mf][nf*2+1], ah[mf], bl[1], bl[3]);
                    mma16816(acc[mf][nf*2+0], al[mf], bh[0], bh[2]);
                    mma16816(acc[mf][nf*2+1], al[mf], bh[1], bh[3]);
                }
            }
        }
        __syncthreads();
    }

    // epilogue
    #pragma unroll
    for (int mf = 0; mf < 2; mf++) {
        #pragma unroll
        for (int nf = 0; nf < 8; nf++) {
            const int row0 = bm + wm + mf*16 + (lane >> 2);
            const int col  = bn + wn + nf*8 + ((lane & 3) << 1);
            float2 b2 = *(const float2*)(bias + col);
            #pragma unroll
            for (int half = 0; half < 2; half++) {
                const int rw = row0 + half*8;
                if (rw >= M_) continue;
                float2 v = make_float2(acc[mf][nf][half*2+0] + b2.x,
                                       acc[mf][nf][half*2+1] + b2.y);
                const size_t o = (size_t)rw * N_ + col;
                if (EPI == 2) {
                    float2 rr = *(const float2*)(res + o);
                    v.x += rr.x; v.y += rr.y;
                }
                if (EPI == 1) {
                    v.x = fmaxf(v.x, 0.f); v.y = fmaxf(v.y, 0.f);
                    split2(v, Ch + o, Cl + o);
                } else {
                    *(float2*)(C + o) = v;
                }
            }
        }
    }
#undef LOADG
#undef STST
}

// ---------------- attention: one block per (b, h) ---------------------------
#define PADK 196
#define PADL 132
#define ATTN_SMEM ((LW*PADK + HDc*PADL + 8*768 + 132) * 4)

__global__ __launch_bounds__(256, 1) void attn_kernel(
        const float* __restrict__ qkv,
        const float* __restrict__ wvalid,
        __nv_bfloat16* __restrict__ cth,
        __nv_bfloat16* __restrict__ ctl) {
    const int h = blockIdx.x, b = blockIdx.y;
    extern __shared__ float sm[];
    float* Ks   = sm;                    // [LW][196]
    float* Vt   = Ks + LW * PADK;        // [192][132] transposed
    float* sq   = Vt + HDc * PADL;       // 8 warps x 768
    float* madd = sq + 8 * 768;          // 132
    const int tid = threadIdx.x, w = tid >> 5, lane = tid & 31;

    const float* base = qkv + (size_t)(b * LW) * H3 + h * HDc;
    for (int idx = tid; idx < LW * HDc; idx += 256) {
        int rr = idx / HDc, c = idx - rr * HDc;
        Ks[rr * PADK + c] = base[(size_t)rr * H3 + Hc + c];
        Vt[c * PADL + rr] = base[(size_t)rr * H3 + 2*Hc + c];
    }
    if (tid < HDc) {
        Vt[tid * PADL + 129] = 0.f;
        Vt[tid * PADL + 130] = 0.f;
        Vt[tid * PADL + 131] = 0.f;
    }
    for (int kk = tid; kk < LW; kk += 256)
        madd[kk] = (kk == 0 || wvalid[b * Wc + kk - 1] > 0.5f) ? 0.f : -3.0e38f;
    __syncthreads();

    const float scale = 0.07216878364870323f; // 1/sqrt(192)
    float* myq = sq + w * 768;

    for (int q0 = w * 4; q0 < LW; q0 += 32) {
        const int nq = (LW - q0 < 4) ? (LW - q0) : 4;
        #pragma unroll
        for (int t = 0; t < 4; t++) {
            if (t < nq) {
                const float* qr = qkv + (size_t)(b * LW + q0 + t) * H3 + h * HDc;
                for (int j = lane; j < 48; j += 32)
                    *(float4*)&myq[t*192 + j*4] = *(const float4*)&qr[j*4];
            } else {
                for (int j = lane; j < 48; j += 32)
                    *(float4*)&myq[t*192 + j*4] = make_float4(0.f,0.f,0.f,0.f);
            }
        }
        __syncwarp();

        float s[4][4];
        #pragma unroll
        for (int t = 0; t < 4; t++)
            #pragma unroll
            for (int i = 0; i < 4; i++) s[t][i] = 0.f;

        #pragma unroll 2
        for (int d4 = 0; d4 < HDc; d4 += 4) {
            float4 qv[4];
            qv[0] = *(const float4*)&myq[0*192 + d4];
            qv[1] = *(const float4*)&myq[1*192 + d4];
            qv[2] = *(const float4*)&myq[2*192 + d4];
            qv[3] = *(const float4*)&myq[3*192 + d4];
            float4 kv[4];
            kv[0] = *(const float4*)&Ks[(lane      ) * PADK + d4];
            kv[1] = *(const float4*)&Ks[(lane + 32 ) * PADK + d4];
            kv[2] = *(const float4*)&Ks[(lane + 64 ) * PADK + d4];
            kv[3] = *(const float4*)&Ks[(lane + 96 ) * PADK + d4];
            #pragma unroll
            for (int t = 0; t < 4; t++)
                #pragma unroll
                for (int i = 0; i < 4; i++)
                    s[t][i] += qv[t].x*kv[i].x + qv[t].y*kv[i].y
                             + qv[t].z*kv[i].z + qv[t].w*kv[i].w;
        }

        float s128[4];
        #pragma unroll
        for (int t = 0; t < 4; t++) {
            float p = 0.f;
            #pragma unroll
            for (int j = 0; j < 6; j++)
                p += myq[t*192 + lane + 32*j] * Ks[128 * PADK + lane + 32*j];
            #pragma unroll
            for (int o = 16; o > 0; o >>= 1) p += __shfl_xor_sync(0xffffffffu, p, o);
            s128[t] = p;
        }

        const float m0 = madd[lane], m1 = madd[lane+32], m2 = madd[lane+64], m3 = madd[lane+96];
        const float m128 = madd[128];
        float e[4][4], e128[4], inv[4];
        #pragma unroll
        for (int t = 0; t < 4; t++) {
            s[t][0] = s[t][0]*scale + m0;
            s[t][1] = s[t][1]*scale + m1;
            s[t][2] = s[t][2]*scale + m2;
            s[t][3] = s[t][3]*scale + m3;
            s128[t] = s128[t]*scale + m128;
            float mm = fmaxf(fmaxf(s[t][0], s[t][1]), fmaxf(s[t][2], s[t][3]));
            #pragma unroll
            for (int o = 16; o > 0; o >>= 1) mm = fmaxf(mm, __shfl_xor_sync(0xffffffffu, mm, o));
            mm = fmaxf(mm, s128[t]);
            e[t][0] = expf(s[t][0] - mm); e[t][1] = expf(s[t][1] - mm);
            e[t][2] = expf(s[t][2] - mm); e[t][3] = expf(s[t][3] - mm);
            float ss = e[t][0] + e[t][1] + e[t][2] + e[t][3];
            #pragma unroll
            for (int o = 16; o > 0; o >>= 1) ss += __shfl_xor_sync(0xffffffffu, ss, o);
            e128[t] = expf(s128[t] - mm);
            ss += e128[t];
            inv[t] = 1.f / ss;
        }
        __syncwarp();
        #pragma unroll
        for (int t = 0; t < 4; t++) {
            myq[t*192 + lane     ] = e[t][0];
            myq[t*192 + lane + 32] = e[t][1];
            myq[t*192 + lane + 64] = e[t][2];
            myq[t*192 + lane + 96] = e[t][3];
            if (lane == 0) myq[t*192 + 128] = e128[t];
            if (lane >= 1 && lane <= 3) myq[t*192 + 128 + lane] = 0.f;
        }
        __syncwarp();

        // AV: acc[t][j] over d = lane+32j, float4 across keys
        float acc[4][6];
        #pragma unroll
        for (int t = 0; t < 4; t++)
            #pragma unroll
            for (int j = 0; j < 6; j++) acc[t][j] = 0.f;
        #pragma unroll 2
        for (int kk4 = 0; kk4 < 132; kk4 += 4) {
            float4 p0 = *(const float4*)&myq[0*192 + kk4];
            float4 p1 = *(const float4*)&myq[1*192 + kk4];
            float4 p2 = *(const float4*)&myq[2*192 + kk4];
            float4 p3 = *(const float4*)&myq[3*192 + kk4];
            #pragma unroll
            for (int j = 0; j < 6; j++) {
                float4 v = *(const float4*)&Vt[(lane + 32*j) * PADL + kk4];
                acc[0][j] += p0.x*v.x + p0.y*v.y + p0.z*v.z + p0.w*v.w;
                acc[1][j] += p1.x*v.x + p1.y*v.y + p1.z*v.z + p1.w*v.w;
                acc[2][j] += p2.x*v.x + p2.y*v.y + p2.z*v.z + p2.w*v.w;
                acc[3][j] += p3.x*v.x + p3.y*v.y + p3.z*v.z + p3.w*v.w;
            }
        }
        for (int t = 0; t < nq; t++) {
            size_t ro = (size_t)(b * LW + q0 + t) * Hc + h * HDc;
            #pragma unroll
            for (int j = 0; j < 6; j++) {
                float val = acc[t][j] * inv[t];
                split1(val, cth + ro + lane + 32*j, ctl + ro + lane + 32*j);
            }
        }
        __syncwarp();
    }
}

// ---------------- layernorm over H=768 per row + hi/lo ----------------------
__global__ void ln_kernel(const float* __restrict__ y,
                          const float* __restrict__ s,
                          const float* __restrict__ bi,
                          float* __restrict__ x,
                          __nv_bfloat16* __restrict__ xh,
                          __nv_bfloat16* __restrict__ xl) {
    int row = blockIdx.x;
    int tid = threadIdx.x;
    __shared__ float red[256];
    const float* yr = y + (size_t)row * Hc;
    float v0 = yr[tid], v1 = yr[tid+256], v2 = yr[tid+512];
    red[tid] = v0 + v1 + v2; __syncthreads();
    for (int o = 128; o > 0; o >>= 1) { if (tid < o) red[tid] += red[tid+o]; __syncthreads(); }
    float mean = red[0] * (1.f/768.f);
    __syncthreads();
    float d0 = v0-mean, d1 = v1-mean, d2 = v2-mean;
    red[tid] = d0*d0 + d1*d1 + d2*d2; __syncthreads();
    for (int o = 128; o > 0; o >>= 1) { if (tid < o) red[tid] += red[tid+o]; __syncthreads(); }
    float inv = rsqrtf(red[0] * (1.f/768.f) + 1e-5f);
    size_t ro = (size_t)row * Hc;
    float o0 = d0*inv*s[tid]     + bi[tid];
    float o1 = d1*inv*s[tid+256] + bi[tid+256];
    float o2 = d2*inv*s[tid+512] + bi[tid+512];
    x[ro+tid] = o0; x[ro+tid+256] = o1; x[ro+tid+512] = o2;
    split1(o0, xh + ro + tid,     xl + ro + tid);
    split1(o1, xh + ro + tid+256, xl + ro + tid+256);
    split1(o2, xh + ro + tid+512, xl + ro + tid+512);
}

// ---------------- classifier + pooled copy ----------------------------------
__global__ void cls_kernel(const float* __restrict__ x,
                           const float* __restrict__ cw,
                           const float* __restrict__ cb,
                           float* __restrict__ out) {
    int b = blockIdx.x;
    int tid = threadIdx.x;
    __shared__ float red[256];
    const float* row = x + (size_t)(b*LW) * Hc;
    out[Bc*NLABc + b*Hc + tid]     = row[tid];
    out[Bc*NLABc + b*Hc + tid+256] = row[tid+256];
    out[Bc*NLABc + b*Hc + tid+512] = row[tid+512];
    for (int lab = 0; lab < NLABc; lab++) {
        const float* wr = cw + lab*Hc;
        float s = row[tid]*wr[tid] + row[tid+256]*wr[tid+256] + row[tid+512]*wr[tid+512];
        red[tid] = s; __syncthreads();
        for (int o = 128; o > 0; o >>= 1) { if (tid < o) red[tid] += red[tid+o]; __syncthreads(); }
        if (tid == 0) out[b*NLABc + lab] = red[0] + cb[lab];
        __syncthreads();
    }
}

// ---------------- launch -----------------------------------------------------
extern "C" void kernel_launch(void* const* d_in, const int* in_sizes, int n_in,
                              void* d_out, int out_size) {
    (void)in_sizes; (void)n_in; (void)out_size;
    const float* hidden = (const float*)d_in[0];
    const int*   widx   = (const int*)  d_in[1];
    const void*  gmask  = d_in[2];
    const void*  wvin   = d_in[3];
    const float* qkv_w  = (const float*)d_in[4];
    const float* qkv_b  = (const float*)d_in[5];
    const float* out_w  = (const float*)d_in[6];
    const float* out_b  = (const float*)d_in[7];
    const float* ff1_w  = (const float*)d_in[8];
    const float* ff1_b  = (const float*)d_in[9];
    const float* ff2_w  = (const float*)d_in[10];
    const float* ff2_b  = (const float*)d_in[11];
    const float* ln1_s  = (const float*)d_in[12];
    const float* ln1_b  = (const float*)d_in[13];
    const float* ln2_s  = (const float*)d_in[14];
    const float* ln2_b  = (const float*)d_in[15];
    const float* cls_w  = (const float*)d_in[16];
    const float* cls_b  = (const float*)d_in[17];
    float* out = (float*)d_out;

    float *x, *qkv, *y, *wval;
    __nv_bfloat16 *wh, *wl, *xh, *xl, *cth, *ctl, *fh, *fl;
    cudaGetSymbolAddress((void**)&x,    g_x);
    cudaGetSymbolAddress((void**)&qkv,  g_qkv);
    cudaGetSymbolAddress((void**)&y,    g_y);
    cudaGetSymbolAddress((void**)&wval, g_wvalid);
    cudaGetSymbolAddress((void**)&wh,   g_wh);
    cudaGetSymbolAddress((void**)&wl,   g_wl);
    cudaGetSymbolAddress((void**)&xh,   g_xh);
    cudaGetSymbolAddress((void**)&xl,   g_xl);
    cudaGetSymbolAddress((void**)&cth,  g_cth);
    cudaGetSymbolAddress((void**)&ctl,  g_ctl);
    cudaGetSymbolAddress((void**)&fh,   g_fh);
    cudaGetSymbolAddress((void**)&fl,   g_fl);

    cudaFuncSetAttribute(hgemm_kernel<0>, cudaFuncAttributeMaxDynamicSharedMemorySize, (int)GEMM_SMEM);
    cudaFuncSetAttribute(hgemm_kernel<1>, cudaFuncAttributeMaxDynamicSharedMemorySize, (int)GEMM_SMEM);
    cudaFuncSetAttribute(hgemm_kernel<2>, cudaFuncAttributeMaxDynamicSharedMemorySize, (int)GEMM_SMEM);
    cudaFuncSetAttribute(attn_kernel,     cudaFuncAttributeMaxDynamicSharedMemorySize, (int)ATTN_SMEM);

    // weight conversion (once per launch)
    wconv_kernel<<<(SZ_QKV/4 + 255)/256, 256>>>(qkv_w, wh + OFF_QKV, wl + OFF_QKV, SZ_QKV);
    wconv_kernel<<<(SZ_OUT/4 + 255)/256, 256>>>(out_w, wh + OFF_OUT, wl + OFF_OUT, SZ_OUT);
    wconv_kernel<<<(SZ_FF1/4 + 255)/256, 256>>>(ff1_w, wh + OFF_FF1, wl + OFF_FF1, SZ_FF1);
    wconv_kernel<<<(SZ_FF2/4 + 255)/256, 256>>>(ff2_w, wh + OFF_FF2, wl + OFF_FF2, SZ_FF2);

    detect_kernel<<<1, 256>>>((const unsigned int*)gmask, (const unsigned int*)wvin);
    build_kernel<<<dim3(LW, Bc), 256>>>(hidden, widx, gmask, wvin, x, xh, xl, wval);

    const int MB = (MROWS + 127) / 128;  // 33
    for (int l = 0; l < NLc; l++) {
        hgemm_kernel<0><<<dim3(H3/128, MB), 256, GEMM_SMEM>>>(
            xh, xl, wh + OFF_QKV + (size_t)l*H3*Hc, wl + OFF_QKV + (size_t)l*H3*Hc,
            qkv_b + (size_t)l*H3, nullptr, qkv, nullptr, nullptr,
            MROWS, H3, Hc);
        attn_kernel<<<dim3(NHc, Bc), 256, ATTN_SMEM>>>(qkv, wval, cth, ctl);
        hgemm_kernel<2><<<dim3(Hc/128, MB), 256, GEMM_SMEM>>>(
            cth, ctl, wh + OFF_OUT + (size_t)l*Hc*Hc, wl + OFF_OUT + (size_t)l*Hc*Hc,
            out_b + (size_t)l*Hc, x, y, nullptr, nullptr,
            MROWS, Hc, Hc);
        ln_kernel<<<MROWS, 256>>>(y, ln1_s + (size_t)l*Hc, ln1_b + (size_t)l*Hc, x, xh, xl);
        hgemm_kernel<1><<<dim3(FFc/128, MB), 256, GEMM_SMEM>>>(
            xh, xl, wh + OFF_FF1 + (size_t)l*FFc*Hc, wl + OFF_FF1 + (size_t)l*FFc*Hc,
            ff1_b + (size_t)l*FFc, nullptr, nullptr, fh, fl,
            MROWS, FFc, Hc);
        hgemm_kernel<2><<<dim3(Hc/128, MB), 256, GEMM_SMEM>>>(
            fh, fl, wh + OFF_FF2 + (size_t)l*Hc*FFc, wl + OFF_FF2 + (size_t)l*Hc*FFc,
            ff2_b + (size_t)l*Hc, x, y, nullptr, nullptr,
            MROWS, Hc, FFc);
        ln_kernel<<<MROWS, 256>>>(y, ln2_s + (size_t)l*Hc, ln2_b + (size_t)l*Hc, x, xh, xl);
    }
    cls_kernel<<<Bc, 256>>>(x, cls_w, cls_b, out);
}